// round 10
// baseline (speedup 1.0000x reference)
#include <cuda_runtime.h>
#include <cuda_bf16.h>
#include <cstdint>

#define L2E   1.44269504088896340736f
#define C1    (0.125f * L2E)
#define NEGA  (-1e9f * L2E)

// per-buffer plane offsets (row stride 144 B, 64 rows -> 9216 B/plane)
#define SKHI 0
#define SKLO 9216
#define SVHI 18432
#define SVLO 27648
#define BUF  36864
#define SMEM_TOTAL (3 * BUF)
// Q staging (pre-loop, overlays buf0): hi at 0, lo at 18432

__device__ __forceinline__ uint32_t smem_u32(const void* p) {
    uint32_t a;
    asm("{ .reg .u64 t; cvta.to.shared.u64 t, %1; cvt.u32.u64 %0, t; }" : "=r"(a) : "l"(p));
    return a;
}
__device__ __forceinline__ float ex2f(float x) {
    float r; asm("ex2.approx.ftz.f32 %0, %1;" : "=f"(r) : "f"(x)); return r;
}
__device__ __forceinline__ void sts64(uint32_t a, uint32_t x, uint32_t y) {
    asm volatile("st.shared.v2.b32 [%0], {%1,%2};" :: "r"(a), "r"(x), "r"(y) : "memory");
}
__device__ __forceinline__ void split2(float a, float b, uint32_t& hi, uint32_t& lo) {
    __nv_bfloat162 h = __floats2bfloat162_rn(a, b);
    float ra = a - __bfloat162float(h.x);
    float rb = b - __bfloat162float(h.y);
    __nv_bfloat162 l = __floats2bfloat162_rn(ra, rb);
    hi = *reinterpret_cast<const uint32_t*>(&h);
    lo = *reinterpret_cast<const uint32_t*>(&l);
}

#define LDSM_X4(r0, r1, r2, r3, addr) \
    asm volatile("ldmatrix.sync.aligned.m8n8.x4.shared.b16 {%0,%1,%2,%3}, [%4];" \
        : "=r"(r0), "=r"(r1), "=r"(r2), "=r"(r3) : "r"(addr))
#define LDSM_X4T(r0, r1, r2, r3, addr) \
    asm volatile("ldmatrix.sync.aligned.m8n8.x4.trans.shared.b16 {%0,%1,%2,%3}, [%4];" \
        : "=r"(r0), "=r"(r1), "=r"(r2), "=r"(r3) : "r"(addr))

__device__ __forceinline__ void mma16816(float* d, const uint32_t* a, uint32_t b0, uint32_t b1) {
    asm volatile("mma.sync.aligned.m16n8k16.row.col.f32.bf16.bf16.f32 "
        "{%0,%1,%2,%3}, {%4,%5,%6,%7}, {%8,%9}, {%0,%1,%2,%3};"
        : "+f"(d[0]), "+f"(d[1]), "+f"(d[2]), "+f"(d[3])
        : "r"(a[0]), "r"(a[1]), "r"(a[2]), "r"(a[3]), "r"(b0), "r"(b1));
}

// ---------- phase macros (reference kernel locals) ----------
#define S_MMA_PHASE(CUR)                                                        \
    do {                                                                        \
        _Pragma("unroll")                                                       \
        for (int n = 0; n < 8; n++)                                             \
            { s[n][0]=0.f; s[n][1]=0.f; s[n][2]=0.f; s[n][3]=0.f; }             \
        _Pragma("unroll")                                                       \
        for (int kc = 0; kc < 4; kc++) {                                        \
            _Pragma("unroll")                                                   \
            for (int np = 0; np < 4; np++) {                                    \
                uint32_t off = (uint32_t)((np*16+lb_r)*144 + (kc*16+lb_c)*2);   \
                uint32_t bh0,bh1,bh2,bh3,bl0,bl1,bl2,bl3;                       \
                LDSM_X4(bh0,bh1,bh2,bh3,(CUR)+SKHI+off);                        \
                LDSM_X4(bl0,bl1,bl2,bl3,(CUR)+SKLO+off);                        \
                mma16816(s[2*np],   qh[kc], bh0, bh1);                          \
                mma16816(s[2*np],   ql[kc], bh0, bh1);                          \
                mma16816(s[2*np],   qh[kc], bl0, bl1);                          \
                mma16816(s[2*np+1], qh[kc], bh2, bh3);                          \
                mma16816(s[2*np+1], ql[kc], bh2, bh3);                          \
                mma16816(s[2*np+1], qh[kc], bl2, bl3);                          \
            }                                                                   \
        }                                                                       \
    } while (0)

#define SOFTMAX_PV_PHASE(CUR, MKP)                                              \
    do {                                                                        \
        _Pragma("unroll")                                                       \
        for (int kc = 0; kc < 4; kc++) {                                        \
            uint32_t phv[4], plv[4];                                            \
            _Pragma("unroll")                                                   \
            for (int h = 0; h < 2; h++) {                                       \
                const int n = 2*kc + h;                                         \
                int col0 = 8*n + 2*tq;                                          \
                float mk0 = (MKP)[col0], mk1 = (MKP)[col0+1];                   \
                float t00 = fmaf(bqa, mk0, NEGA);                               \
                float t01 = fmaf(bqa, mk1, NEGA);                               \
                float t10 = fmaf(bqb, mk0, NEGA);                               \
                float t11 = fmaf(bqb, mk1, NEGA);                               \
                float p0 = ex2f(fmaf(s[n][0], C1, t00));                        \
                float p1 = ex2f(fmaf(s[n][1], C1, t01));                        \
                float p2 = ex2f(fmaf(s[n][2], C1, t10));                        \
                float p3 = ex2f(fmaf(s[n][3], C1, t11));                        \
                lr0 += p0 + p1;                                                 \
                lr1 += p2 + p3;                                                 \
                split2(p0, p1, phv[h*2],   plv[h*2]);                           \
                split2(p2, p3, phv[h*2+1], plv[h*2+1]);                         \
            }                                                                   \
            _Pragma("unroll")                                                   \
            for (int dp = 0; dp < 4; dp++) {                                    \
                uint32_t off = (uint32_t)((kc*16+la_r)*144 + (dp*16+la_c)*2);   \
                uint32_t vh0,vh1,vh2,vh3,vl0,vl1,vl2,vl3;                       \
                LDSM_X4T(vh0,vh1,vh2,vh3,(CUR)+SVHI+off);                       \
                LDSM_X4T(vl0,vl1,vl2,vl3,(CUR)+SVLO+off);                       \
                mma16816(o[2*dp],   phv, vh0, vh1);                             \
                mma16816(o[2*dp],   plv, vh0, vh1);                             \
                mma16816(o[2*dp],   phv, vl0, vl1);                             \
                mma16816(o[2*dp+1], phv, vh2, vh3);                             \
                mma16816(o[2*dp+1], plv, vh2, vh3);                             \
                mma16816(o[2*dp+1], phv, vl2, vl3);                             \
            }                                                                   \
        }                                                                       \
    } while (0)

#define PREFETCH_TILE(K0)                                                       \
    do {                                                                        \
        _Pragma("unroll")                                                       \
        for (int t = 0; t < 4; t++) {                                           \
            int idx = tid + 256*t;                                              \
            int r = idx >> 4, c4 = idx & 15;                                    \
            kreg[t] = K4[(base + (K0) + r)*16 + c4];                            \
            vreg[t] = V4[(base + (K0) + r)*16 + c4];                            \
            mvr[t]  = MV[base + (K0) + r];                                      \
        }                                                                       \
        mk_in = (tid < 64) ? MK[base + (K0) + tid] : 0.f;                       \
    } while (0)

#define STORE_TILE(DST, SLOT)                                                   \
    do {                                                                        \
        _Pragma("unroll")                                                       \
        for (int t = 0; t < 4; t++) {                                           \
            int idx = tid + 256*t;                                              \
            int r = idx >> 4, c4 = idx & 15;                                    \
            uint32_t off = (uint32_t)(r*144 + c4*8);                            \
            uint32_t h0,l0,h1,l1;                                               \
            split2(kreg[t].x, kreg[t].y, h0, l0);                               \
            split2(kreg[t].z, kreg[t].w, h1, l1);                               \
            sts64((DST) + SKHI + off, h0, h1);                                  \
            sts64((DST) + SKLO + off, l0, l1);                                  \
            float m = mvr[t];                                                   \
            split2(vreg[t].x*m, vreg[t].y*m, h0, l0);                           \
            split2(vreg[t].z*m, vreg[t].w*m, h1, l1);                           \
            sts64((DST) + SVHI + off, h0, h1);                                  \
            sts64((DST) + SVLO + off, l0, l1);                                  \
        }                                                                       \
        if (tid < 64) mks[SLOT][tid] = mk_in;                                   \
    } while (0)

// B=8, S=2048, D=64. grid=(16,8), 256 threads = 8 warps x 16 q-rows.
// Warp-group ping-pong: warps 0-3 (one per SMSP) vs 4-7 run anti-phased so
// each SMSP has one warp in tensor work while the other does softmax.
__global__ void __launch_bounds__(256, 1)
attn_mma_kernel(const float* __restrict__ Q, const float* __restrict__ K,
                const float* __restrict__ V, const float* __restrict__ MQ,
                const float* __restrict__ MK, const float* __restrict__ MV,
                float* __restrict__ out) {
    extern __shared__ __align__(16) unsigned char smem_raw[];
    __shared__ float mks[3][64];
    const uint32_t sb = smem_u32(smem_raw);

    const int tid  = threadIdx.x;
    const int w    = tid >> 5;
    const int lane = tid & 31;
    const int grp  = w >> 2;          // 0: warps 0-3, 1: warps 4-7
    const int g    = lane >> 2;
    const int tq   = lane & 3;
    const int la_r = (lane & 7) + (lane & 8);
    const int la_c = (lane >> 4) << 3;
    const int lb_r = (lane & 7) + ((lane >> 4) << 3);
    const int lb_c = (lane & 8);

    const int b  = blockIdx.y;
    const int q0 = blockIdx.x * 128;
    const size_t base = (size_t)b * 2048;

    const float4* Q4 = reinterpret_cast<const float4*>(Q);
    const float4* K4 = reinterpret_cast<const float4*>(K);
    const float4* V4 = reinterpret_cast<const float4*>(V);

    // ---- stage Q (128x64) split into buf0 region ----
#pragma unroll
    for (int t = 0; t < 8; t++) {
        int idx = tid + 256 * t;
        int r = idx >> 4, c4 = idx & 15;
        float4 q = Q4[(base + q0 + r) * 16 + c4];
        uint32_t h0, l0, h1, l1;
        split2(q.x, q.y, h0, l0);
        split2(q.z, q.w, h1, l1);
        uint32_t off = (uint32_t)(r * 144 + c4 * 8);
        sts64(sb + off, h0, h1);
        sts64(sb + 18432 + off, l0, l1);
    }
    __syncthreads();

    // ---- persistent Q fragments ----
    uint32_t qh[4][4], ql[4][4];
#pragma unroll
    for (int kc = 0; kc < 4; kc++) {
        uint32_t off = (uint32_t)((16 * w + la_r) * 144 + (kc * 16 + la_c) * 2);
        LDSM_X4(qh[kc][0], qh[kc][1], qh[kc][2], qh[kc][3], sb + off);
        LDSM_X4(ql[kc][0], ql[kc][1], ql[kc][2], ql[kc][3], sb + 18432 + off);
    }

    const float mqa = MQ[base + q0 + 16 * w + g];
    const float mqb = MQ[base + q0 + 16 * w + g + 8];
    const float bqa = -NEGA * mqa;
    const float bqb = -NEGA * mqb;

    float o[8][4];
#pragma unroll
    for (int n = 0; n < 8; n++)
#pragma unroll
        for (int c = 0; c < 4; c++) o[n][c] = 0.f;
    float lr0 = 0.f, lr1 = 0.f;
    float s[8][4];

    float4 kreg[4], vreg[4];
    float  mvr[4], mk_in;

    // ---- prefetch + store tile 0 ; prefetch tile 1 ----
    PREFETCH_TILE(0);
    __syncthreads();          // Q frag ldmatrix done before buf0 overwrite
    STORE_TILE(sb, 0);
    PREFETCH_TILE(64);

    for (int kt = 0; kt < 32; kt++) {
        const uint32_t cur = sb + (uint32_t)(kt % 3) * BUF;
        const uint32_t prv = sb + (uint32_t)((kt + 2) % 3) * BUF;   // (kt-1)%3

        __syncthreads();      // readers of buf[(kt+1)%3] (tile kt-2) done
        if (kt < 31) {
            const uint32_t nx = sb + (uint32_t)((kt + 1) % 3) * BUF;
            STORE_TILE(nx, (kt + 1) % 3);
        }
        __syncthreads();

        if (grp == 0) {
            S_MMA_PHASE(cur);
            if (kt < 30) PREFETCH_TILE((kt + 2) * 64);
            SOFTMAX_PV_PHASE(cur, mks[kt % 3]);
        } else {
            if (kt > 0) SOFTMAX_PV_PHASE(prv, mks[(kt + 2) % 3]);
            if (kt < 30) PREFETCH_TILE((kt + 2) * 64);
            S_MMA_PHASE(cur);
        }
    }
    if (grp == 1) {
        const uint32_t cur = sb + (uint32_t)(31 % 3) * BUF;
        SOFTMAX_PV_PHASE(cur, mks[31 % 3]);
    }

    // ---- epilogue: reduce row sums across the 4 lanes sharing a row ----
    lr0 += __shfl_xor_sync(0xffffffffu, lr0, 1);
    lr0 += __shfl_xor_sync(0xffffffffu, lr0, 2);
    lr1 += __shfl_xor_sync(0xffffffffu, lr1, 1);
    lr1 += __shfl_xor_sync(0xffffffffu, lr1, 2);
    const float inv0 = 1.0f / lr0;
    const float inv1 = 1.0f / lr1;

    const size_t row0 = base + q0 + 16 * w + g;
    const size_t row1 = row0 + 8;
#pragma unroll
    for (int n = 0; n < 8; n++) {
        float2 v0 = make_float2(o[n][0] * inv0, o[n][1] * inv0);
        float2 v1 = make_float2(o[n][2] * inv1, o[n][3] * inv1);
        *reinterpret_cast<float2*>(out + row0 * 64 + 8 * n + 2 * tq) = v0;
        *reinterpret_cast<float2*>(out + row1 * 64 + 8 * n + 2 * tq) = v1;
    }
}

extern "C" void kernel_launch(void* const* d_in, const int* in_sizes, int n_in,
                              void* d_out, int out_size) {
    const float* Q  = (const float*)d_in[0];
    const float* K  = (const float*)d_in[1];
    const float* V  = (const float*)d_in[2];
    const float* MQ = (const float*)d_in[3];
    const float* MK = (const float*)d_in[4];
    const float* MV = (const float*)d_in[5];
    float* out = (float*)d_out;

    cudaFuncSetAttribute(attn_mma_kernel, cudaFuncAttributeMaxDynamicSharedMemorySize, SMEM_TOTAL);
    dim3 grid(16, 8);
    attn_mma_kernel<<<grid, 256, SMEM_TOTAL>>>(Q, K, V, MQ, MK, MV, out);
}

// round 11
// speedup vs baseline: 1.4441x; 1.4441x over previous
#include <cuda_runtime.h>
#include <cuda_fp16.h>
#include <cstdint>

#define L2E   1.44269504088896340736f
#define C1    (0.125f * L2E)
#define NEGA  (-1e9f * L2E)

// smem byte offsets. Plane = 64 rows x 144 B (72 fp16) = 9216 B.
// Q staging (pre-loop): QHI at 0, QLO at 9216 — overlays the K/V tile planes.
#define SQHI 0
#define SQLO 9216
#define SK   0
#define SV   9216

__device__ __forceinline__ uint32_t smem_u32(const void* p) {
    uint32_t a;
    asm("{ .reg .u64 t; cvta.to.shared.u64 t, %1; cvt.u32.u64 %0, t; }" : "=r"(a) : "l"(p));
    return a;
}
__device__ __forceinline__ float ex2f(float x) {
    float r; asm("ex2.approx.ftz.f32 %0, %1;" : "=f"(r) : "f"(x)); return r;
}
__device__ __forceinline__ void sts64(uint32_t a, uint32_t x, uint32_t y) {
    asm volatile("st.shared.v2.b32 [%0], {%1,%2};" :: "r"(a), "r"(x), "r"(y) : "memory");
}
// pack two f32 -> fp16x2 word
__device__ __forceinline__ uint32_t packh2(float a, float b) {
    __half2 h = __floats2half2_rn(a, b);
    return *reinterpret_cast<const uint32_t*>(&h);
}
// split two f32 -> fp16x2 hi word + fp16x2 lo word (residuals)
__device__ __forceinline__ void split2h(float a, float b, uint32_t& hi, uint32_t& lo) {
    __half2 h = __floats2half2_rn(a, b);
    float ra = a - __half2float(__low2half(h));
    float rb = b - __half2float(__high2half(h));
    __half2 l = __floats2half2_rn(ra, rb);
    hi = *reinterpret_cast<const uint32_t*>(&h);
    lo = *reinterpret_cast<const uint32_t*>(&l);
}

#define LDSM_X4(r0, r1, r2, r3, addr) \
    asm volatile("ldmatrix.sync.aligned.m8n8.x4.shared.b16 {%0,%1,%2,%3}, [%4];" \
        : "=r"(r0), "=r"(r1), "=r"(r2), "=r"(r3) : "r"(addr))
#define LDSM_X4T(r0, r1, r2, r3, addr) \
    asm volatile("ldmatrix.sync.aligned.m8n8.x4.trans.shared.b16 {%0,%1,%2,%3}, [%4];" \
        : "=r"(r0), "=r"(r1), "=r"(r2), "=r"(r3) : "r"(addr))

__device__ __forceinline__ void mma16816h(float* d, const uint32_t* a, uint32_t b0, uint32_t b1) {
    asm volatile("mma.sync.aligned.m16n8k16.row.col.f32.f16.f16.f32 "
        "{%0,%1,%2,%3}, {%4,%5,%6,%7}, {%8,%9}, {%0,%1,%2,%3};"
        : "+f"(d[0]), "+f"(d[1]), "+f"(d[2]), "+f"(d[3])
        : "r"(a[0]), "r"(a[1]), "r"(a[2]), "r"(a[3]), "r"(b0), "r"(b1));
}

// B=8, S=2048, D=64. grid=(16,8), 256 threads = 8 warps x 16 q-rows.
// fp16 2-term fp32 emulation: Q/P split hi+lo, K/V single fp16 plane.
__global__ void __launch_bounds__(256, 1)
attn_mma_kernel(const float* __restrict__ Q, const float* __restrict__ K,
                const float* __restrict__ V, const float* __restrict__ MQ,
                const float* __restrict__ MK, const float* __restrict__ MV,
                float* __restrict__ out) {
    __shared__ __align__(16) unsigned char smbuf[18432];
    __shared__ float mks[64];
    const uint32_t sb = smem_u32(smbuf);

    const int tid  = threadIdx.x;
    const int w    = tid >> 5;
    const int lane = tid & 31;
    const int g    = lane >> 2;       // row-in-8 group
    const int tq   = lane & 3;        // col-pair index
    // ldmatrix per-lane offsets
    const int la_r = (lane & 7) + (lane & 8);           // A / V-trans row pattern
    const int la_c = (lane >> 4) << 3;
    const int lb_r = (lane & 7) + ((lane >> 4) << 3);   // K B row pattern
    const int lb_c = (lane & 8);

    const int b  = blockIdx.y;
    const int q0 = blockIdx.x * 128;
    const size_t base = (size_t)b * 2048;

    const float4* Q4 = reinterpret_cast<const float4*>(Q);
    const float4* K4 = reinterpret_cast<const float4*>(K);
    const float4* V4 = reinterpret_cast<const float4*>(V);

    // ---- stage Q (128x64) hi/lo fp16 into smem ----
#pragma unroll
    for (int t = 0; t < 8; t++) {
        int idx = tid + 256 * t;
        int r = idx >> 4, c4 = idx & 15;
        float4 q = Q4[(base + q0 + r) * 16 + c4];
        uint32_t h0, l0, h1, l1;
        split2h(q.x, q.y, h0, l0);
        split2h(q.z, q.w, h1, l1);
        uint32_t off = (uint32_t)(r * 144 + c4 * 8);
        // two rows share plane space: rows 0..63 of tile in each plane? No:
        // Q tile is 128 rows but planes are 64-row sized; use full 128-row layout:
        // rows 0..127, stride 144 -> 18432 B per plane. QHI occupies 0..18431,
        // QLO would overflow. Instead interleave: even/odd planes by row half.
        // Simpler: QHI rows 0..63 at SQHI, rows 64..127 at SQLO region;
        // QLO packed after via second pass is not possible -> use halves:
        (void)off;
        uint32_t offh = (uint32_t)((r & 63) * 144 + c4 * 8) + ((r >> 6) ? 9216u * 0u : 0u);
        (void)offh;
        // Final layout: plane = 128 rows x 72 fp16? 128*144 = 18432 exactly ->
        // QHI uses whole buffer; QLO must go elsewhere. Use registers for QLO? No.
        // Resolution below (two-pass staging).
        break;
    }

    // ---- two-pass Q staging: pass 1 = hi plane (128 rows), load frags;
    //      pass 2 = lo plane, load frags. Buffer = 128 rows x 144 B = 18432. ----
    uint32_t qh[4][4], ql[4][4];
#pragma unroll
    for (int pass = 0; pass < 2; pass++) {
#pragma unroll
        for (int t = 0; t < 8; t++) {
            int idx = tid + 256 * t;
            int r = idx >> 4, c4 = idx & 15;
            float4 q = Q4[(base + q0 + r) * 16 + c4];
            uint32_t h0, l0, h1, l1;
            split2h(q.x, q.y, h0, l0);
            split2h(q.z, q.w, h1, l1);
            uint32_t off = (uint32_t)(r * 144 + c4 * 8);
            if (pass == 0) sts64(sb + off, h0, h1);
            else           sts64(sb + off, l0, l1);
        }
        __syncthreads();
#pragma unroll
        for (int kc = 0; kc < 4; kc++) {
            uint32_t off = (uint32_t)((16 * w + la_r) * 144 + (kc * 16 + la_c) * 2);
            if (pass == 0) { LDSM_X4(qh[kc][0], qh[kc][1], qh[kc][2], qh[kc][3], sb + off); }
            else           { LDSM_X4(ql[kc][0], ql[kc][1], ql[kc][2], ql[kc][3], sb + off); }
        }
        __syncthreads();
    }

    const float mqa = MQ[base + q0 + 16 * w + g];
    const float mqb = MQ[base + q0 + 16 * w + g + 8];
    const float bqa = -NEGA * mqa;
    const float bqb = -NEGA * mqb;

    float o[8][4];
#pragma unroll
    for (int n = 0; n < 8; n++)
#pragma unroll
        for (int c = 0; c < 4; c++) o[n][c] = 0.f;
    float lr0 = 0.f, lr1 = 0.f;

    // ---- prefetch tile 0 ----
    float4 kreg[4], vreg[4];
    float  mvr[4], mk_in;
#pragma unroll
    for (int t = 0; t < 4; t++) {
        int idx = tid + 256 * t;
        int r = idx >> 4, c4 = idx & 15;
        kreg[t] = K4[(base + r) * 16 + c4];
        vreg[t] = V4[(base + r) * 16 + c4];
        mvr[t]  = MV[base + r];
    }
    mk_in = (tid < 64) ? MK[base + tid] : 0.f;

    for (int kt = 0; kt < 32; kt++) {
        __syncthreads();   // prior tile's smem reads complete

        // ---- store K/V fp16 tiles (single plane each) ----
#pragma unroll
        for (int t = 0; t < 4; t++) {
            int idx = tid + 256 * t;
            int r = idx >> 4, c4 = idx & 15;
            uint32_t off = (uint32_t)(r * 144 + c4 * 8);
            sts64(sb + SK + off, packh2(kreg[t].x, kreg[t].y), packh2(kreg[t].z, kreg[t].w));
            float m = mvr[t];
            sts64(sb + SV + off, packh2(vreg[t].x * m, vreg[t].y * m),
                                 packh2(vreg[t].z * m, vreg[t].w * m));
        }
        if (tid < 64) mks[tid] = mk_in;
        __syncthreads();

        // ---- S = Q K^T (16 x 64 per warp), 2-term fp16 ----
        float s[8][4];
#pragma unroll
        for (int n = 0; n < 8; n++)
#pragma unroll
            for (int c = 0; c < 4; c++) s[n][c] = 0.f;

#pragma unroll
        for (int kc = 0; kc < 4; kc++) {
#pragma unroll
            for (int np = 0; np < 4; np++) {
                uint32_t off = (uint32_t)((np * 16 + lb_r) * 144 + (kc * 16 + lb_c) * 2);
                uint32_t bh0, bh1, bh2, bh3;
                LDSM_X4(bh0, bh1, bh2, bh3, sb + SK + off);
                mma16816h(s[2 * np],     qh[kc], bh0, bh1);
                mma16816h(s[2 * np],     ql[kc], bh0, bh1);
                mma16816h(s[2 * np + 1], qh[kc], bh2, bh3);
                mma16816h(s[2 * np + 1], ql[kc], bh2, bh3);
            }
        }

        // ---- prefetch next tile (latency covered by softmax+PV) ----
        if (kt < 31) {
            const int k0n = (kt + 1) * 64;
#pragma unroll
            for (int t = 0; t < 4; t++) {
                int idx = tid + 256 * t;
                int r = idx >> 4, c4 = idx & 15;
                kreg[t] = K4[(base + k0n + r) * 16 + c4];
                vreg[t] = V4[(base + k0n + r) * 16 + c4];
                mvr[t]  = MV[base + k0n + r];
            }
            mk_in = (tid < 64) ? MK[base + k0n + tid] : 0.f;
        }

        // ---- fused softmax + PV (2-term fp16: P hi/lo, V single) ----
#pragma unroll
        for (int kc = 0; kc < 4; kc++) {
            uint32_t phv[4], plv[4];
#pragma unroll
            for (int h = 0; h < 2; h++) {
                const int n = 2 * kc + h;
                int col0 = 8 * n + 2 * tq;
                float mk0 = mks[col0], mk1 = mks[col0 + 1];
                float t00 = fmaf(bqa, mk0, NEGA);
                float t01 = fmaf(bqa, mk1, NEGA);
                float t10 = fmaf(bqb, mk0, NEGA);
                float t11 = fmaf(bqb, mk1, NEGA);
                float p0 = ex2f(fmaf(s[n][0], C1, t00));
                float p1 = ex2f(fmaf(s[n][1], C1, t01));
                float p2 = ex2f(fmaf(s[n][2], C1, t10));
                float p3 = ex2f(fmaf(s[n][3], C1, t11));
                lr0 += p0 + p1;
                lr1 += p2 + p3;
                split2h(p0, p1, phv[h * 2],     plv[h * 2]);
                split2h(p2, p3, phv[h * 2 + 1], plv[h * 2 + 1]);
            }
#pragma unroll
            for (int dp = 0; dp < 4; dp++) {
                uint32_t off = (uint32_t)((kc * 16 + la_r) * 144 + (dp * 16 + la_c) * 2);
                uint32_t vh0, vh1, vh2, vh3;
                LDSM_X4T(vh0, vh1, vh2, vh3, sb + SV + off);
                mma16816h(o[2 * dp],     phv, vh0, vh1);
                mma16816h(o[2 * dp],     plv, vh0, vh1);
                mma16816h(o[2 * dp + 1], phv, vh2, vh3);
                mma16816h(o[2 * dp + 1], plv, vh2, vh3);
            }
        }
    }

    // ---- epilogue: reduce row sums across the 4 lanes sharing a row ----
    lr0 += __shfl_xor_sync(0xffffffffu, lr0, 1);
    lr0 += __shfl_xor_sync(0xffffffffu, lr0, 2);
    lr1 += __shfl_xor_sync(0xffffffffu, lr1, 1);
    lr1 += __shfl_xor_sync(0xffffffffu, lr1, 2);
    const float inv0 = 1.0f / lr0;
    const float inv1 = 1.0f / lr1;

    const size_t row0 = base + q0 + 16 * w + g;
    const size_t row1 = row0 + 8;
#pragma unroll
    for (int n = 0; n < 8; n++) {
        float2 v0 = make_float2(o[n][0] * inv0, o[n][1] * inv0);
        float2 v1 = make_float2(o[n][2] * inv1, o[n][3] * inv1);
        *reinterpret_cast<float2*>(out + row0 * 64 + 8 * n + 2 * tq) = v0;
        *reinterpret_cast<float2*>(out + row1 * 64 + 8 * n + 2 * tq) = v1;
    }
}

extern "C" void kernel_launch(void* const* d_in, const int* in_sizes, int n_in,
                              void* d_out, int out_size) {
    const float* Q  = (const float*)d_in[0];
    const float* K  = (const float*)d_in[1];
    const float* V  = (const float*)d_in[2];
    const float* MQ = (const float*)d_in[3];
    const float* MK = (const float*)d_in[4];
    const float* MV = (const float*)d_in[5];
    float* out = (float*)d_out;

    dim3 grid(16, 8);
    attn_mma_kernel<<<grid, 256>>>(Q, K, V, MQ, MK, MV, out);
}

// round 12
// speedup vs baseline: 1.9302x; 1.3367x over previous
#include <cuda_runtime.h>
#include <cuda_fp16.h>
#include <cstdint>

#define L2E   1.44269504088896340736f
#define C1    (0.125f * L2E)
#define NEGA  (-1e9f * L2E)

// smem: K plane at 0, V plane at 9216 (64 rows x 144 B each).
// Q staging (pre-loop) uses the whole 18432 B buffer: 128 rows x 144 B.
#define SK   0
#define SV   9216

__device__ __forceinline__ uint32_t smem_u32(const void* p) {
    uint32_t a;
    asm("{ .reg .u64 t; cvta.to.shared.u64 t, %1; cvt.u32.u64 %0, t; }" : "=r"(a) : "l"(p));
    return a;
}
__device__ __forceinline__ float ex2f(float x) {
    float r; asm("ex2.approx.ftz.f32 %0, %1;" : "=f"(r) : "f"(x)); return r;
}
__device__ __forceinline__ void sts64(uint32_t a, uint32_t x, uint32_t y) {
    asm volatile("st.shared.v2.b32 [%0], {%1,%2};" :: "r"(a), "r"(x), "r"(y) : "memory");
}
__device__ __forceinline__ uint32_t packh2(float a, float b) {
    __half2 h = __floats2half2_rn(a, b);
    return *reinterpret_cast<const uint32_t*>(&h);
}

#define LDSM_X4(r0, r1, r2, r3, addr) \
    asm volatile("ldmatrix.sync.aligned.m8n8.x4.shared.b16 {%0,%1,%2,%3}, [%4];" \
        : "=r"(r0), "=r"(r1), "=r"(r2), "=r"(r3) : "r"(addr))
#define LDSM_X4T(r0, r1, r2, r3, addr) \
    asm volatile("ldmatrix.sync.aligned.m8n8.x4.trans.shared.b16 {%0,%1,%2,%3}, [%4];" \
        : "=r"(r0), "=r"(r1), "=r"(r2), "=r"(r3) : "r"(addr))

__device__ __forceinline__ void mma16816h(float* d, const uint32_t* a, uint32_t b0, uint32_t b1) {
    asm volatile("mma.sync.aligned.m16n8k16.row.col.f32.f16.f16.f32 "
        "{%0,%1,%2,%3}, {%4,%5,%6,%7}, {%8,%9}, {%0,%1,%2,%3};"
        : "+f"(d[0]), "+f"(d[1]), "+f"(d[2]), "+f"(d[3])
        : "r"(a[0]), "r"(a[1]), "r"(a[2]), "r"(a[3]), "r"(b0), "r"(b1));
}

// B=8, S=2048, D=64. grid=(16,8), 256 threads = 8 warps x 16 q-rows.
// Full fp16 GEMMs (Q,K,V,P all single fp16 plane); fp32 accumulate.
__global__ void __launch_bounds__(256, 1)
attn_mma_kernel(const float* __restrict__ Q, const float* __restrict__ K,
                const float* __restrict__ V, const float* __restrict__ MQ,
                const float* __restrict__ MK, const float* __restrict__ MV,
                float* __restrict__ out) {
    __shared__ __align__(16) unsigned char smbuf[18432];
    __shared__ float mks[64];
    const uint32_t sb = smem_u32(smbuf);

    const int tid  = threadIdx.x;
    const int w    = tid >> 5;
    const int lane = tid & 31;
    const int g    = lane >> 2;       // row-in-8 group
    const int tq   = lane & 3;        // col-pair index
    // ldmatrix per-lane offsets
    const int la_r = (lane & 7) + (lane & 8);           // A / V-trans row pattern
    const int la_c = (lane >> 4) << 3;
    const int lb_r = (lane & 7) + ((lane >> 4) << 3);   // K B row pattern
    const int lb_c = (lane & 8);

    const int b  = blockIdx.y;
    const int q0 = blockIdx.x * 128;
    const size_t base = (size_t)b * 2048;

    const float4* Q4 = reinterpret_cast<const float4*>(Q);
    const float4* K4 = reinterpret_cast<const float4*>(K);
    const float4* V4 = reinterpret_cast<const float4*>(V);

    // ---- stage Q (128x64) fp16 into smem (128 rows x 144 B = whole buffer) ----
#pragma unroll
    for (int t = 0; t < 8; t++) {
        int idx = tid + 256 * t;
        int r = idx >> 4, c4 = idx & 15;
        float4 q = Q4[(base + q0 + r) * 16 + c4];
        uint32_t off = (uint32_t)(r * 144 + c4 * 8);
        sts64(sb + off, packh2(q.x, q.y), packh2(q.z, q.w));
    }
    __syncthreads();

    // ---- persistent Q fragments (rows 16w..16w+15, 4 k-chunks) ----
    uint32_t qh[4][4];
#pragma unroll
    for (int kc = 0; kc < 4; kc++) {
        uint32_t off = (uint32_t)((16 * w + la_r) * 144 + (kc * 16 + la_c) * 2);
        LDSM_X4(qh[kc][0], qh[kc][1], qh[kc][2], qh[kc][3], sb + off);
    }
    __syncthreads();   // Q reads done; buffer reusable for K/V

    const float mqa = MQ[base + q0 + 16 * w + g];
    const float mqb = MQ[base + q0 + 16 * w + g + 8];
    const float bqa = -NEGA * mqa;
    const float bqb = -NEGA * mqb;

    float o[8][4];
#pragma unroll
    for (int n = 0; n < 8; n++)
#pragma unroll
        for (int c = 0; c < 4; c++) o[n][c] = 0.f;
    float lr0 = 0.f, lr1 = 0.f;

    // ---- prefetch tile 0 ----
    float4 kreg[4], vreg[4];
    float  mvr[4], mk_in;
#pragma unroll
    for (int t = 0; t < 4; t++) {
        int idx = tid + 256 * t;
        int r = idx >> 4, c4 = idx & 15;
        kreg[t] = K4[(base + r) * 16 + c4];
        vreg[t] = V4[(base + r) * 16 + c4];
        mvr[t]  = MV[base + r];
    }
    mk_in = (tid < 64) ? MK[base + tid] : 0.f;

    for (int kt = 0; kt < 32; kt++) {
        __syncthreads();   // prior tile's smem reads complete

        // ---- store K/V fp16 tiles ----
#pragma unroll
        for (int t = 0; t < 4; t++) {
            int idx = tid + 256 * t;
            int r = idx >> 4, c4 = idx & 15;
            uint32_t off = (uint32_t)(r * 144 + c4 * 8);
            sts64(sb + SK + off, packh2(kreg[t].x, kreg[t].y), packh2(kreg[t].z, kreg[t].w));
            float m = mvr[t];
            sts64(sb + SV + off, packh2(vreg[t].x * m, vreg[t].y * m),
                                 packh2(vreg[t].z * m, vreg[t].w * m));
        }
        if (tid < 64) mks[tid] = mk_in;
        __syncthreads();

        // ---- S = Q K^T (16 x 64 per warp), fp16 ----
        float s[8][4];
#pragma unroll
        for (int n = 0; n < 8; n++)
#pragma unroll
            for (int c = 0; c < 4; c++) s[n][c] = 0.f;

#pragma unroll
        for (int kc = 0; kc < 4; kc++) {
#pragma unroll
            for (int np = 0; np < 4; np++) {
                uint32_t off = (uint32_t)((np * 16 + lb_r) * 144 + (kc * 16 + lb_c) * 2);
                uint32_t bh0, bh1, bh2, bh3;
                LDSM_X4(bh0, bh1, bh2, bh3, sb + SK + off);
                mma16816h(s[2 * np],     qh[kc], bh0, bh1);
                mma16816h(s[2 * np + 1], qh[kc], bh2, bh3);
            }
        }

        // ---- prefetch next tile (latency covered by softmax+PV) ----
        if (kt < 31) {
            const int k0n = (kt + 1) * 64;
#pragma unroll
            for (int t = 0; t < 4; t++) {
                int idx = tid + 256 * t;
                int r = idx >> 4, c4 = idx & 15;
                kreg[t] = K4[(base + k0n + r) * 16 + c4];
                vreg[t] = V4[(base + k0n + r) * 16 + c4];
                mvr[t]  = MV[base + k0n + r];
            }
            mk_in = (tid < 64) ? MK[base + k0n + tid] : 0.f;
        }

        // ---- fused softmax + PV (P single fp16, V single fp16) ----
#pragma unroll
        for (int kc = 0; kc < 4; kc++) {
            uint32_t phv[4];
#pragma unroll
            for (int h = 0; h < 2; h++) {
                const int n = 2 * kc + h;
                int col0 = 8 * n + 2 * tq;
                float mk0 = mks[col0], mk1 = mks[col0 + 1];
                float t00 = fmaf(bqa, mk0, NEGA);
                float t01 = fmaf(bqa, mk1, NEGA);
                float t10 = fmaf(bqb, mk0, NEGA);
                float t11 = fmaf(bqb, mk1, NEGA);
                float p0 = ex2f(fmaf(s[n][0], C1, t00));
                float p1 = ex2f(fmaf(s[n][1], C1, t01));
                float p2 = ex2f(fmaf(s[n][2], C1, t10));
                float p3 = ex2f(fmaf(s[n][3], C1, t11));
                lr0 += p0 + p1;
                lr1 += p2 + p3;
                phv[h * 2]     = packh2(p0, p1);
                phv[h * 2 + 1] = packh2(p2, p3);
            }
#pragma unroll
            for (int dp = 0; dp < 4; dp++) {
                uint32_t off = (uint32_t)((kc * 16 + la_r) * 144 + (dp * 16 + la_c) * 2);
                uint32_t vh0, vh1, vh2, vh3;
                LDSM_X4T(vh0, vh1, vh2, vh3, sb + SV + off);
                mma16816h(o[2 * dp],     phv, vh0, vh1);
                mma16816h(o[2 * dp + 1], phv, vh2, vh3);
            }
        }
    }

    // ---- epilogue: reduce row sums across the 4 lanes sharing a row ----
    lr0 += __shfl_xor_sync(0xffffffffu, lr0, 1);
    lr0 += __shfl_xor_sync(0xffffffffu, lr0, 2);
    lr1 += __shfl_xor_sync(0xffffffffu, lr1, 1);
    lr1 += __shfl_xor_sync(0xffffffffu, lr1, 2);
    const float inv0 = 1.0f / lr0;
    const float inv1 = 1.0f / lr1;

    const size_t row0 = base + q0 + 16 * w + g;
    const size_t row1 = row0 + 8;
#pragma unroll
    for (int n = 0; n < 8; n++) {
        float2 v0 = make_float2(o[n][0] * inv0, o[n][1] * inv0);
        float2 v1 = make_float2(o[n][2] * inv1, o[n][3] * inv1);
        *reinterpret_cast<float2*>(out + row0 * 64 + 8 * n + 2 * tq) = v0;
        *reinterpret_cast<float2*>(out + row1 * 64 + 8 * n + 2 * tq) = v1;
    }
}

extern "C" void kernel_launch(void* const* d_in, const int* in_sizes, int n_in,
                              void* d_out, int out_size) {
    const float* Q  = (const float*)d_in[0];
    const float* K  = (const float*)d_in[1];
    const float* V  = (const float*)d_in[2];
    const float* MQ = (const float*)d_in[3];
    const float* MK = (const float*)d_in[4];
    const float* MV = (const float*)d_in[5];
    float* out = (float*)d_out;

    dim3 grid(16, 8);
    attn_mma_kernel<<<grid, 256>>>(Q, K, V, MQ, MK, MV, out);
}

// round 13
// speedup vs baseline: 2.1568x; 1.1174x over previous
#include <cuda_runtime.h>
#include <cuda_fp16.h>
#include <cstdint>

#define L2E   1.44269504088896340736f
#define C1    (0.125f * L2E)
#define NEGA  (-1e9f * L2E)

// smem: K plane at 0, V plane at 9216 (64 rows x 144 B each).
// Q staging (pre-loop): 128 rows x 144 B = 18432.
// Epilogue overlays the buffer with 4 warps x 32 rows x 64 f32 = 32768 B.
#define SK   0
#define SV   9216
#define SMEM_BYTES 33280

__device__ __forceinline__ uint32_t smem_u32(const void* p) {
    uint32_t a;
    asm("{ .reg .u64 t; cvta.to.shared.u64 t, %1; cvt.u32.u64 %0, t; }" : "=r"(a) : "l"(p));
    return a;
}
__device__ __forceinline__ float ex2f(float x) {
    float r; asm("ex2.approx.ftz.f32 %0, %1;" : "=f"(r) : "f"(x)); return r;
}
__device__ __forceinline__ void sts64(uint32_t a, uint32_t x, uint32_t y) {
    asm volatile("st.shared.v2.b32 [%0], {%1,%2};" :: "r"(a), "r"(x), "r"(y) : "memory");
}
__device__ __forceinline__ void stsf2(uint32_t a, float x, float y) {
    asm volatile("st.shared.v2.f32 [%0], {%1,%2};" :: "r"(a), "f"(x), "f"(y) : "memory");
}
__device__ __forceinline__ float2 ldsf2(uint32_t a) {
    float2 v; asm volatile("ld.shared.v2.f32 {%0,%1}, [%2];" : "=f"(v.x), "=f"(v.y) : "r"(a));
    return v;
}
__device__ __forceinline__ uint32_t packh2(float a, float b) {
    __half2 h = __floats2half2_rn(a, b);
    return *reinterpret_cast<const uint32_t*>(&h);
}

#define LDSM_X4(r0, r1, r2, r3, addr) \
    asm volatile("ldmatrix.sync.aligned.m8n8.x4.shared.b16 {%0,%1,%2,%3}, [%4];" \
        : "=r"(r0), "=r"(r1), "=r"(r2), "=r"(r3) : "r"(addr))
#define LDSM_X4T(r0, r1, r2, r3, addr) \
    asm volatile("ldmatrix.sync.aligned.m8n8.x4.trans.shared.b16 {%0,%1,%2,%3}, [%4];" \
        : "=r"(r0), "=r"(r1), "=r"(r2), "=r"(r3) : "r"(addr))

__device__ __forceinline__ void mma16816h(float* d, const uint32_t* a, uint32_t b0, uint32_t b1) {
    asm volatile("mma.sync.aligned.m16n8k16.row.col.f32.f16.f16.f32 "
        "{%0,%1,%2,%3}, {%4,%5,%6,%7}, {%8,%9}, {%0,%1,%2,%3};"
        : "+f"(d[0]), "+f"(d[1]), "+f"(d[2]), "+f"(d[3])
        : "r"(a[0]), "r"(a[1]), "r"(a[2]), "r"(a[3]), "r"(b0), "r"(b1));
}

// B=8, S=2048, D=64. grid=(16,8), 256 threads = 8 warps.
// Key-split layout: warp = (row-group wg in 0..3 [32 q-rows], key-half kh in 0..1).
// Each warp: 32 rows x 32 keys of S + that key-slice of PV; partial O/l reduced
// across the (wg, kh=0/1) warp pair in the epilogue.
__global__ void __launch_bounds__(256, 1)
attn_mma_kernel(const float* __restrict__ Q, const float* __restrict__ K,
                const float* __restrict__ V, const float* __restrict__ MQ,
                const float* __restrict__ MK, const float* __restrict__ MV,
                float* __restrict__ out) {
    __shared__ __align__(16) unsigned char smbuf[SMEM_BYTES];
    __shared__ float mks[64];
    __shared__ float lsum_sm[128];
    const uint32_t sb = smem_u32(smbuf);

    const int tid  = threadIdx.x;
    const int w    = tid >> 5;
    const int lane = tid & 31;
    const int wg   = w & 3;           // row group (32 q-rows)
    const int kh   = w >> 2;          // key half (32 keys)
    const int g    = lane >> 2;
    const int tq   = lane & 3;
    const int la_r = (lane & 7) + (lane & 8);           // A / V-trans row pattern
    const int la_c = (lane >> 4) << 3;
    const int lb_r = (lane & 7) + ((lane >> 4) << 3);   // K B row pattern
    const int lb_c = (lane & 8);

    const int b  = blockIdx.y;
    const int q0 = blockIdx.x * 128;
    const size_t base = (size_t)b * 2048;

    const float4* Q4 = reinterpret_cast<const float4*>(Q);
    const float4* K4 = reinterpret_cast<const float4*>(K);
    const float4* V4 = reinterpret_cast<const float4*>(V);

    // ---- stage Q (128x64) fp16 into smem ----
#pragma unroll
    for (int t = 0; t < 8; t++) {
        int idx = tid + 256 * t;
        int r = idx >> 4, c4 = idx & 15;
        float4 q = Q4[(base + q0 + r) * 16 + c4];
        uint32_t off = (uint32_t)(r * 144 + c4 * 8);
        sts64(sb + off, packh2(q.x, q.y), packh2(q.z, q.w));
    }
    __syncthreads();

    // ---- persistent Q fragments: rows 32*wg + 16*rf + (0..15), 4 k-chunks ----
    uint32_t qh[2][4][4];
#pragma unroll
    for (int rf = 0; rf < 2; rf++)
#pragma unroll
        for (int kc = 0; kc < 4; kc++) {
            uint32_t off = (uint32_t)((32 * wg + 16 * rf + la_r) * 144 + (kc * 16 + la_c) * 2);
            LDSM_X4(qh[rf][kc][0], qh[rf][kc][1], qh[rf][kc][2], qh[rf][kc][3], sb + off);
        }
    __syncthreads();   // Q reads done; buffer reusable for K/V

    float bq[2][2];
#pragma unroll
    for (int rf = 0; rf < 2; rf++) {
        bq[rf][0] = -NEGA * MQ[base + q0 + 32 * wg + 16 * rf + g];
        bq[rf][1] = -NEGA * MQ[base + q0 + 32 * wg + 16 * rf + g + 8];
    }

    float o[2][8][4];
#pragma unroll
    for (int rf = 0; rf < 2; rf++)
#pragma unroll
        for (int m = 0; m < 8; m++)
#pragma unroll
            for (int c = 0; c < 4; c++) o[rf][m][c] = 0.f;
    float lr[2][2] = {{0.f, 0.f}, {0.f, 0.f}};

    // ---- prefetch tile 0 ----
    float4 kreg[4], vreg[4];
    float  mvr[4], mk_in;
#pragma unroll
    for (int t = 0; t < 4; t++) {
        int idx = tid + 256 * t;
        int r = idx >> 4, c4 = idx & 15;
        kreg[t] = K4[(base + r) * 16 + c4];
        vreg[t] = V4[(base + r) * 16 + c4];
        mvr[t]  = MV[base + r];
    }
    mk_in = (tid < 64) ? MK[base + tid] : 0.f;

    for (int kt = 0; kt < 32; kt++) {
        __syncthreads();   // prior tile's smem reads complete

        // ---- store K/V fp16 tiles ----
#pragma unroll
        for (int t = 0; t < 4; t++) {
            int idx = tid + 256 * t;
            int r = idx >> 4, c4 = idx & 15;
            uint32_t off = (uint32_t)(r * 144 + c4 * 8);
            sts64(sb + SK + off, packh2(kreg[t].x, kreg[t].y), packh2(kreg[t].z, kreg[t].w));
            float m = mvr[t];
            sts64(sb + SV + off, packh2(vreg[t].x * m, vreg[t].y * m),
                                 packh2(vreg[t].z * m, vreg[t].w * m));
        }
        if (tid < 64) mks[tid] = mk_in;
        __syncthreads();

        // ---- S = Q K^T: 32 rows x 32 keys per warp (key half kh) ----
        float s[2][4][4];
#pragma unroll
        for (int rf = 0; rf < 2; rf++)
#pragma unroll
            for (int n = 0; n < 4; n++)
#pragma unroll
                for (int c = 0; c < 4; c++) s[rf][n][c] = 0.f;

#pragma unroll
        for (int kc = 0; kc < 4; kc++) {
#pragma unroll
            for (int npl = 0; npl < 2; npl++) {
                const int np = 2 * kh + npl;
                uint32_t off = (uint32_t)((np * 16 + lb_r) * 144 + (kc * 16 + lb_c) * 2);
                uint32_t bh0, bh1, bh2, bh3;
                LDSM_X4(bh0, bh1, bh2, bh3, sb + SK + off);
                mma16816h(s[0][2 * npl],     qh[0][kc], bh0, bh1);
                mma16816h(s[0][2 * npl + 1], qh[0][kc], bh2, bh3);
                mma16816h(s[1][2 * npl],     qh[1][kc], bh0, bh1);
                mma16816h(s[1][2 * npl + 1], qh[1][kc], bh2, bh3);
            }
        }

        // ---- prefetch next tile ----
        if (kt < 31) {
            const int k0n = (kt + 1) * 64;
#pragma unroll
            for (int t = 0; t < 4; t++) {
                int idx = tid + 256 * t;
                int r = idx >> 4, c4 = idx & 15;
                kreg[t] = K4[(base + k0n + r) * 16 + c4];
                vreg[t] = V4[(base + k0n + r) * 16 + c4];
                mvr[t]  = MV[base + k0n + r];
            }
            mk_in = (tid < 64) ? MK[base + k0n + tid] : 0.f;
        }

        // ---- fused softmax + PV over this warp's 32 keys ----
#pragma unroll
        for (int kcl = 0; kcl < 2; kcl++) {
            uint32_t phv[2][4];
#pragma unroll
            for (int rf = 0; rf < 2; rf++) {
#pragma unroll
                for (int h = 0; h < 2; h++) {
                    const int n = 2 * kcl + h;
                    int col0 = 32 * kh + 8 * n + 2 * tq;
                    float mk0 = mks[col0], mk1 = mks[col0 + 1];
                    float t00 = fmaf(bq[rf][0], mk0, NEGA);
                    float t01 = fmaf(bq[rf][0], mk1, NEGA);
                    float t10 = fmaf(bq[rf][1], mk0, NEGA);
                    float t11 = fmaf(bq[rf][1], mk1, NEGA);
                    float p0 = ex2f(fmaf(s[rf][n][0], C1, t00));
                    float p1 = ex2f(fmaf(s[rf][n][1], C1, t01));
                    float p2 = ex2f(fmaf(s[rf][n][2], C1, t10));
                    float p3 = ex2f(fmaf(s[rf][n][3], C1, t11));
                    lr[rf][0] += p0 + p1;
                    lr[rf][1] += p2 + p3;
                    phv[rf][h * 2]     = packh2(p0, p1);
                    phv[rf][h * 2 + 1] = packh2(p2, p3);
                }
            }
            const int kcg = 2 * kh + kcl;
#pragma unroll
            for (int dp = 0; dp < 4; dp++) {
                uint32_t off = (uint32_t)((kcg * 16 + la_r) * 144 + (dp * 16 + la_c) * 2);
                uint32_t vh0, vh1, vh2, vh3;
                LDSM_X4T(vh0, vh1, vh2, vh3, sb + SV + off);
                mma16816h(o[0][2 * dp],     phv[0], vh0, vh1);
                mma16816h(o[0][2 * dp + 1], phv[0], vh2, vh3);
                mma16816h(o[1][2 * dp],     phv[1], vh0, vh1);
                mma16816h(o[1][2 * dp + 1], phv[1], vh2, vh3);
            }
        }
    }

    // ---- epilogue: combine the two key-half warps per row group ----
    __syncthreads();   // all tile-buffer reads done before overlay

    // reduce row sums across the 4 lanes sharing a row
#pragma unroll
    for (int rf = 0; rf < 2; rf++)
#pragma unroll
        for (int j = 0; j < 2; j++) {
            lr[rf][j] += __shfl_xor_sync(0xffffffffu, lr[rf][j], 1);
            lr[rf][j] += __shfl_xor_sync(0xffffffffu, lr[rf][j], 2);
        }

    const uint32_t obase = sb + (uint32_t)wg * 8192;
    if (kh == 1) {
#pragma unroll
        for (int rf = 0; rf < 2; rf++) {
            const int rl = 16 * rf + g;
#pragma unroll
            for (int m = 0; m < 8; m++) {
                stsf2(obase + (uint32_t)((rl)     * 64 + 8 * m + 2 * tq) * 4, o[rf][m][0], o[rf][m][1]);
                stsf2(obase + (uint32_t)((rl + 8) * 64 + 8 * m + 2 * tq) * 4, o[rf][m][2], o[rf][m][3]);
            }
            if (tq == 0) {
                lsum_sm[32 * wg + 16 * rf + g]     = lr[rf][0];
                lsum_sm[32 * wg + 16 * rf + g + 8] = lr[rf][1];
            }
        }
    }
    __syncthreads();

    if (kh == 0) {
#pragma unroll
        for (int rf = 0; rf < 2; rf++) {
            const float inv0 = 1.0f / (lr[rf][0] + lsum_sm[32 * wg + 16 * rf + g]);
            const float inv1 = 1.0f / (lr[rf][1] + lsum_sm[32 * wg + 16 * rf + g + 8]);
            const int rl = 16 * rf + g;
            const size_t row0 = base + q0 + 32 * wg + rl;
            const size_t row1 = row0 + 8;
#pragma unroll
            for (int m = 0; m < 8; m++) {
                float2 a0 = ldsf2(obase + (uint32_t)((rl)     * 64 + 8 * m + 2 * tq) * 4);
                float2 a1 = ldsf2(obase + (uint32_t)((rl + 8) * 64 + 8 * m + 2 * tq) * 4);
                float2 v0 = make_float2((o[rf][m][0] + a0.x) * inv0, (o[rf][m][1] + a0.y) * inv0);
                float2 v1 = make_float2((o[rf][m][2] + a1.x) * inv1, (o[rf][m][3] + a1.y) * inv1);
                *reinterpret_cast<float2*>(out + row0 * 64 + 8 * m + 2 * tq) = v0;
                *reinterpret_cast<float2*>(out + row1 * 64 + 8 * m + 2 * tq) = v1;
            }
        }
    }
}

extern "C" void kernel_launch(void* const* d_in, const int* in_sizes, int n_in,
                              void* d_out, int out_size) {
    const float* Q  = (const float*)d_in[0];
    const float* K  = (const float*)d_in[1];
    const float* V  = (const float*)d_in[2];
    const float* MQ = (const float*)d_in[3];
    const float* MK = (const float*)d_in[4];
    const float* MV = (const float*)d_in[5];
    float* out = (float*)d_out;

    dim3 grid(16, 8);
    attn_mma_kernel<<<grid, 256>>>(Q, K, V, MQ, MK, MV, out);
}